// round 7
// baseline (speedup 1.0000x reference)
#include <cuda_runtime.h>
#include <cstdint>

// out[b,t] = sum_w <x1[b,:,(t+w+450)%900,:], x2[b,:,w,:]>
//          = sum over Gram G[b,i,j] = <a1_i, a2_j> along circular diagonals.
// mma.sync tf32 (sm_80 ISA -- harness PTX target is compute_103 without 'a',
// so tcgen05 is unavailable). 16 batched 900x900x1024 GEMMs, 128x128 tiles.

#define W_ 900
#define B_ 16
#define NT 8          // 8 tiles of 128 covering 1024 >= 900
#define TM 128
#define KC 32         // K floats per stage
#define NK 32         // 1024 / 32
#define NTHREADS 256

__device__ float g_part[B_ * NT * NT * 256];

// ---------------- PTX helpers (all plain sm_80-level) ----------------
__device__ __forceinline__ uint32_t smem_u32(const void* p) {
    uint32_t a;
    asm("{ .reg .u64 t; cvta.to.shared.u64 t, %1; cvt.u32.u64 %0, t; }" : "=r"(a) : "l"(p));
    return a;
}
__device__ __forceinline__ void cp16(uint32_t dst, const void* src, int sz) {
    asm volatile("cp.async.cg.shared.global [%0], [%1], 16, %2;"
                 :: "r"(dst), "l"(src), "r"(sz) : "memory");
}
__device__ __forceinline__ void cp_commit() {
    asm volatile("cp.async.commit_group;" ::: "memory");
}
__device__ __forceinline__ void cp_wait2() {
    asm volatile("cp.async.wait_group 2;" ::: "memory");
}
__device__ __forceinline__ void ldm4(uint32_t* r, uint32_t a) {
    asm volatile("ldmatrix.sync.aligned.m8n8.x4.shared.b16 {%0,%1,%2,%3}, [%4];"
                 : "=r"(r[0]), "=r"(r[1]), "=r"(r[2]), "=r"(r[3]) : "r"(a));
}
__device__ __forceinline__ uint32_t tf32r(uint32_t x) {
    uint32_t o; float f = __uint_as_float(x);
    asm("cvt.rna.tf32.f32 %0, %1;" : "=r"(o) : "f"(f));
    return o;
}
__device__ __forceinline__ void mma_t(float* c, const uint32_t* a, uint32_t b0, uint32_t b1) {
    asm volatile("mma.sync.aligned.m16n8k8.row.col.f32.tf32.tf32.f32 "
                 "{%0,%1,%2,%3}, {%4,%5,%6,%7}, {%8,%9}, {%0,%1,%2,%3};"
                 : "+f"(c[0]), "+f"(c[1]), "+f"(c[2]), "+f"(c[3])
                 : "r"(a[0]), "r"(a[1]), "r"(a[2]), "r"(a[3]), "r"(b0), "r"(b1));
}

// Issue one K-stage of cp.async loads (A tile + B tile, zfill past row 899).
__device__ __forceinline__ void issue_stage(
    int s, const float* __restrict__ x1, const float* __restrict__ x2,
    int b, int i0, int j0, uint32_t sbase, int crow, int cchk)
{
    const int buf = s & 3;
    const int h  = (s * KC) >> 8;
    const int cb = (s * KC) & 255;
    const float* baseA = x1 + (size_t)(b * 4 + h) * W_ * 256 + cb + cchk * 4;
    const float* baseB = x2 + (size_t)(b * 4 + h) * W_ * 256 + cb + cchk * 4;
    const uint32_t dA0 = sbase + (uint32_t)buf * 32768u;
#pragma unroll
    for (int q = 0; q < 4; ++q) {
        int row = q * 32 + crow;
        uint32_t doff = (uint32_t)row * 128u + (uint32_t)((cchk ^ (row & 7)) << 4);
        int ga = i0 + row;
        int gb = j0 + row;
        int szA = (ga < W_) ? 16 : 0; if (ga >= W_) ga = 0;
        int szB = (gb < W_) ? 16 : 0; if (gb >= W_) gb = 0;
        cp16(dA0 + doff,          baseA + (size_t)ga * 256, szA);
        cp16(dA0 + 16384u + doff, baseB + (size_t)gb * 256, szB);
    }
    cp_commit();
}

// ---------------- main GEMM kernel ----------------
__global__ __launch_bounds__(NTHREADS, 1)
void corr_mma(const float* __restrict__ x1, const float* __restrict__ x2) {
    extern __shared__ float smem[];
    const uint32_t sbase = smem_u32(smem);

    const int tid  = threadIdx.x;
    const int lane = tid & 31;
    const int wid  = tid >> 5;
    const int warp_m = wid & 3;    // 4 warps along i (32 rows each)
    const int warp_n = wid >> 2;   // 2 warps along j (64 cols each)

    const int bx = blockIdx.x;
    const int tj = bx & 7;
    const int ti = (bx >> 3) & 7;
    const int b  = bx >> 6;
    const int i0 = ti * TM;
    const int j0 = tj * TM;

    float acc[2][8][4];
#pragma unroll
    for (int m = 0; m < 2; ++m)
#pragma unroll
        for (int n = 0; n < 8; ++n)
#pragma unroll
            for (int k = 0; k < 4; ++k) acc[m][n][k] = 0.f;

    // cp.async per-thread mapping: 16B chunk cchk of row crow (+32 per q)
    const int crow = tid >> 3;
    const int cchk = tid & 7;

    // ldmatrix per-thread row bases: thread supplies row (lane&7) of matrix (lane>>3)
    const int qm = lane >> 3;
    const int lr = lane & 7;
    const int qh = qm >> 1;        // k-half select (chunk offset)
    const int ql = qm & 1;         // +8 rows select
    const int rA = warp_m * 32 + ql * 8 + lr;   // + mt*16
    const int rB = warp_n * 64 + ql * 8 + lr;   // + np*16

    issue_stage(0, x1, x2, b, i0, j0, sbase, crow, cchk);
    issue_stage(1, x1, x2, b, i0, j0, sbase, crow, cchk);
    issue_stage(2, x1, x2, b, i0, j0, sbase, crow, cchk);

    for (int s = 0; s < NK; ++s) {
        cp_wait2();
        __syncthreads();   // stage s data visible to all; all warps done with buf (s-1)&3
        if (s + 3 < NK) issue_stage(s + 3, x1, x2, b, i0, j0, sbase, crow, cchk);
        else            cp_commit();   // empty group keeps wait_group 2 semantics exact

        const uint32_t Ab = sbase + (uint32_t)(s & 3) * 32768u;
        const uint32_t Bb = Ab + 16384u;

#pragma unroll
        for (int kk = 0; kk < 4; ++kk) {
            uint32_t a[2][4], bf[4][4];
#pragma unroll
            for (int mt = 0; mt < 2; ++mt) {
                int row = rA + mt * 16;
                ldm4(a[mt], Ab + (uint32_t)row * 128u
                               + (uint32_t)(((2 * kk + qh) ^ (row & 7)) << 4));
            }
#pragma unroll
            for (int np = 0; np < 4; ++np) {
                int row = rB + np * 16;
                ldm4(bf[np], Bb + (uint32_t)row * 128u
                                + (uint32_t)(((2 * kk + qh) ^ (row & 7)) << 4));
            }
            // round-to-nearest fp32 -> tf32 (kills truncation bias)
#pragma unroll
            for (int mt = 0; mt < 2; ++mt)
#pragma unroll
                for (int r = 0; r < 4; ++r) a[mt][r] = tf32r(a[mt][r]);
#pragma unroll
            for (int np = 0; np < 4; ++np)
#pragma unroll
                for (int r = 0; r < 4; ++r) bf[np][r] = tf32r(bf[np][r]);

#pragma unroll
            for (int mt = 0; mt < 2; ++mt) {
#pragma unroll
                for (int nt = 0; nt < 8; ++nt) {
                    const int np = nt >> 1;
                    uint32_t b0 = (nt & 1) ? bf[np][1] : bf[np][0];
                    uint32_t b1 = (nt & 1) ? bf[np][3] : bf[np][2];
                    mma_t(acc[mt][nt], a[mt], b0, b1);
                }
            }
        }
    }

    // ---------------- epilogue: stage tile, bin diagonals ----------------
    __syncthreads();                 // all compute done before smem reuse
    float* stg = smem;               // 128 x 132 floats = 67.5KB (fits in 128KB)
#pragma unroll
    for (int mt = 0; mt < 2; ++mt) {
        const int row0 = warp_m * 32 + mt * 16 + (lane >> 2);
#pragma unroll
        for (int nt = 0; nt < 8; ++nt) {
            const int col = warp_n * 64 + nt * 8 + (lane & 3) * 2;
            stg[row0 * 132 + col]       = acc[mt][nt][0];
            stg[row0 * 132 + col + 1]   = acc[mt][nt][1];
            stg[(row0 + 8) * 132 + col]     = acc[mt][nt][2];
            stg[(row0 + 8) * 132 + col + 1] = acc[mt][nt][3];
        }
    }
    __syncthreads();

    if (tid < 255) {
        const int d = tid - 127;                    // diag i - j in [-127, 127]
        const int ilo = d > 0 ? d : 0;
        const int ihi = d < 0 ? 127 + d : 127;
        float sum = 0.f;
        for (int i = ilo; i <= ihi; ++i)
            sum += stg[i * 132 + (i - d)];
        g_part[bx * 256 + tid] = sum;
    }
}

// ---------------- final reduction: tile-diagonals -> out[b,t] ----------------
__global__ void reduce_kernel(float* __restrict__ out) {
    const int idx = blockIdx.x * blockDim.x + threadIdx.x;
    if (idx >= B_ * W_) return;
    const int b = idx / W_;
    const int t = idx - b * W_;
    float s = 0.f;
#pragma unroll
    for (int ti = 0; ti < NT; ++ti) {
#pragma unroll
        for (int tj = 0; tj < NT; ++tj) {
            int m = (t + 450 - TM * (ti - tj)) % 900;
            if (m < 0) m += 900;
            int d;
            if (m <= 127)      d = m;
            else if (m >= 773) d = m - 900;
            else               continue;
            s += g_part[((b * NT + ti) * NT + tj) * 256 + d + 127];
        }
    }
    out[idx] = s;
}

extern "C" void kernel_launch(void* const* d_in, const int* in_sizes, int n_in,
                              void* d_out, int out_size) {
    const float* x1 = (const float*)d_in[0];
    const float* x2 = (const float*)d_in[1];
    float* out = (float*)d_out;

    cudaFuncSetAttribute(corr_mma,
                         cudaFuncAttributeMaxDynamicSharedMemorySize, 131072);
    corr_mma<<<B_ * NT * NT, NTHREADS, 131072>>>(x1, x2);
    reduce_kernel<<<(B_ * W_ + 255) / 256, 256>>>(out);
}

// round 8
// speedup vs baseline: 1.6744x; 1.6744x over previous
#include <cuda_runtime.h>
#include <cstdint>

// out[b,t] = sum_w <x1[b,:,(t+w+450)%900,:], x2[b,:,w,:]>
//          = circular-diagonal sums of Gram G[b,i,j] = <a1_i, a2_j>.
// tf32 mma.sync (compute_103 PTX target: no tcgen05). Prepass rounds inputs
// to tf32 once; GEMM CTA tile 128x256, 512 threads (4 warps/SMSP), 4-stage
// cp.async pipeline in 192KB smem; diagonal-bin epilogue; warp-shuffle reduce.

#define W_ 900
#define B_ 16
#define NTI 8         // i tiles of 128  (1024)
#define NTJ 4         // j tiles of 256  (1024)
#define TM 128
#define TN 256
#define KC 32         // K floats per stage
#define NK 32         // 1024 / KC
#define NTHREADS 512

#define STAGE_A 16384u          // 128 rows x 128B
#define STAGE_B 32768u          // 256 rows x 128B
#define STAGE   49152u
#define SMEM_BYTES (4u * STAGE) // 196608

#define NELEM (B_ * 4 * W_ * 256)   // 14,745,600 per tensor

__device__ float g_x1t[NELEM];
__device__ float g_x2t[NELEM];
__device__ float g_part[B_ * NTI * NTJ * 512];

// ---------------- PTX helpers ----------------
__device__ __forceinline__ uint32_t smem_u32(const void* p) {
    uint32_t a;
    asm("{ .reg .u64 t; cvta.to.shared.u64 t, %1; cvt.u32.u64 %0, t; }" : "=r"(a) : "l"(p));
    return a;
}
__device__ __forceinline__ void cp16(uint32_t dst, const void* src, int sz) {
    asm volatile("cp.async.cg.shared.global [%0], [%1], 16, %2;"
                 :: "r"(dst), "l"(src), "r"(sz) : "memory");
}
__device__ __forceinline__ void cp_commit() {
    asm volatile("cp.async.commit_group;" ::: "memory");
}
__device__ __forceinline__ void cp_wait2() {
    asm volatile("cp.async.wait_group 2;" ::: "memory");
}
__device__ __forceinline__ void cp_wait0() {
    asm volatile("cp.async.wait_group 0;" ::: "memory");
}
__device__ __forceinline__ void ldm4(uint32_t* r, uint32_t a) {
    asm volatile("ldmatrix.sync.aligned.m8n8.x4.shared.b16 {%0,%1,%2,%3}, [%4];"
                 : "=r"(r[0]), "=r"(r[1]), "=r"(r[2]), "=r"(r[3]) : "r"(a));
}
__device__ __forceinline__ float tf32r(float x) {
    uint32_t o;
    asm("cvt.rna.tf32.f32 %0, %1;" : "=r"(o) : "f"(x));
    return __uint_as_float(o);
}
__device__ __forceinline__ void mma_t(float* c, const uint32_t* a, uint32_t b0, uint32_t b1) {
    asm volatile("mma.sync.aligned.m16n8k8.row.col.f32.tf32.tf32.f32 "
                 "{%0,%1,%2,%3}, {%4,%5,%6,%7}, {%8,%9}, {%0,%1,%2,%3};"
                 : "+f"(c[0]), "+f"(c[1]), "+f"(c[2]), "+f"(c[3])
                 : "r"(a[0]), "r"(a[1]), "r"(a[2]), "r"(a[3]), "r"(b0), "r"(b1));
}

// ---------------- prepass: fp32 -> tf32(rna) into scratch ----------------
__global__ __launch_bounds__(256)
void prepass_kernel(const float4* __restrict__ x1, const float4* __restrict__ x2) {
    const int n4 = NELEM / 4;
    float4* o1 = reinterpret_cast<float4*>(g_x1t);
    float4* o2 = reinterpret_cast<float4*>(g_x2t);
    for (int i = blockIdx.x * blockDim.x + threadIdx.x; i < n4;
         i += gridDim.x * blockDim.x) {
        float4 v = x1[i];
        o1[i] = make_float4(tf32r(v.x), tf32r(v.y), tf32r(v.z), tf32r(v.w));
        float4 u = x2[i];
        o2[i] = make_float4(tf32r(u.x), tf32r(u.y), tf32r(u.z), tf32r(u.w));
    }
}

__global__ void dummy_kernel() {}

// ---------------- stage loader ----------------
__device__ __forceinline__ void issue_stage(
    int s, int b, int i0, int j0, uint32_t sbase, int crow, int cchk)
{
    const int buf = s & 3;
    const int h  = (s * KC) >> 8;
    const int cb = (s * KC) & 255;
    const float* baseA = g_x1t + (size_t)(b * 4 + h) * W_ * 256 + cb + cchk * 4;
    const float* baseB = g_x2t + (size_t)(b * 4 + h) * W_ * 256 + cb + cchk * 4;
    const uint32_t dA0 = sbase + (uint32_t)buf * STAGE;
    const uint32_t dB0 = dA0 + STAGE_A;
#pragma unroll
    for (int q = 0; q < 2; ++q) {            // A: 128 rows
        int row = q * 64 + crow;
        uint32_t doff = (uint32_t)row * 128u + (uint32_t)((cchk ^ (row & 7)) << 4);
        int ga = i0 + row;
        int sz = (ga < W_) ? 16 : 0; if (ga >= W_) ga = 0;
        cp16(dA0 + doff, baseA + (size_t)ga * 256, sz);
    }
#pragma unroll
    for (int q = 0; q < 4; ++q) {            // B: 256 rows
        int row = q * 64 + crow;
        uint32_t doff = (uint32_t)row * 128u + (uint32_t)((cchk ^ (row & 7)) << 4);
        int gb = j0 + row;
        int sz = (gb < W_) ? 16 : 0; if (gb >= W_) gb = 0;
        cp16(dB0 + doff, baseB + (size_t)gb * 256, sz);
    }
    cp_commit();
}

// ---------------- main GEMM kernel ----------------
__global__ __launch_bounds__(NTHREADS, 1)
void corr_mma(int unused) {
    extern __shared__ float smem[];
    const uint32_t sbase = smem_u32(smem);

    const int tid  = threadIdx.x;
    const int lane = tid & 31;
    const int wid  = tid >> 5;
    const int warp_m = wid & 3;    // 4 warps along i (32 rows)
    const int warp_n = wid >> 2;   // 4 warps along j (64 cols)

    const int bx = blockIdx.x;
    const int tj = bx & 3;
    const int ti = (bx >> 2) & 7;
    const int b  = bx >> 5;
    const int i0 = ti * TM;
    const int j0 = tj * TN;

    float acc[2][8][4];
#pragma unroll
    for (int m = 0; m < 2; ++m)
#pragma unroll
        for (int n = 0; n < 8; ++n)
#pragma unroll
            for (int k = 0; k < 4; ++k) acc[m][n][k] = 0.f;

    const int crow = tid >> 3;     // 0..63
    const int cchk = tid & 7;

    const int qm = lane >> 3;
    const int lr = lane & 7;
    const int qh = qm >> 1;
    const int ql = qm & 1;
    const int rA = warp_m * 32 + ql * 8 + lr;
    const int rB = warp_n * 64 + ql * 8 + lr;

    issue_stage(0, b, i0, j0, sbase, crow, cchk);
    issue_stage(1, b, i0, j0, sbase, crow, cchk);
    issue_stage(2, b, i0, j0, sbase, crow, cchk);

    for (int s = 0; s < NK; ++s) {
        cp_wait2();
        __syncthreads();
        if (s + 3 < NK) issue_stage(s + 3, b, i0, j0, sbase, crow, cchk);
        else            cp_commit();   // keep wait_group arithmetic exact

        const uint32_t Ab = sbase + (uint32_t)(s & 3) * STAGE;
        const uint32_t Bb = Ab + STAGE_A;

#pragma unroll
        for (int kk = 0; kk < 4; ++kk) {
            uint32_t a[2][4], bf[4][4];
#pragma unroll
            for (int mt = 0; mt < 2; ++mt) {
                int row = rA + mt * 16;
                ldm4(a[mt], Ab + (uint32_t)row * 128u
                               + (uint32_t)(((2 * kk + qh) ^ (row & 7)) << 4));
            }
#pragma unroll
            for (int np = 0; np < 4; ++np) {
                int row = rB + np * 16;
                ldm4(bf[np], Bb + (uint32_t)row * 128u
                                + (uint32_t)(((2 * kk + qh) ^ (row & 7)) << 4));
            }
#pragma unroll
            for (int mt = 0; mt < 2; ++mt) {
#pragma unroll
                for (int nt = 0; nt < 8; ++nt) {
                    const int np = nt >> 1;
                    uint32_t b0 = (nt & 1) ? bf[np][1] : bf[np][0];
                    uint32_t b1 = (nt & 1) ? bf[np][3] : bf[np][2];
                    mma_t(acc[mt][nt], a[mt], b0, b1);
                }
            }
        }
    }

    // drain all cp.async before reusing smem for staging
    cp_wait0();
    __syncthreads();

    // ---------------- epilogue: stage tile, bin diagonals ----------------
    float* stg = smem;                        // 128 x 260 floats = 133KB
#pragma unroll
    for (int mt = 0; mt < 2; ++mt) {
        const int row0 = warp_m * 32 + mt * 16 + (lane >> 2);
#pragma unroll
        for (int nt = 0; nt < 8; ++nt) {
            const int col = warp_n * 64 + nt * 8 + (lane & 3) * 2;
            stg[row0 * 260 + col]           = acc[mt][nt][0];
            stg[row0 * 260 + col + 1]       = acc[mt][nt][1];
            stg[(row0 + 8) * 260 + col]     = acc[mt][nt][2];
            stg[(row0 + 8) * 260 + col + 1] = acc[mt][nt][3];
        }
    }
    __syncthreads();

    if (tid < 383) {                          // d = i - j in [-255, 127]
        const int d = tid - 255;
        const int ilo = d > 0 ? d : 0;
        const int ihi = (255 + d < 127) ? 255 + d : 127;
        float sum = 0.f;
        for (int i = ilo; i <= ihi; ++i)
            sum += stg[i * 260 + (i - d)];
        g_part[bx * 512 + tid] = sum;
    }
}

// ---------------- reduce: one warp per (b,t), lane = (ti,tj) ----------------
__global__ __launch_bounds__(256)
void reduce_kernel(float* __restrict__ out) {
    const int w = blockIdx.x * 8 + (threadIdx.x >> 5);
    if (w >= B_ * W_) return;
    const int lane = threadIdx.x & 31;
    const int b = w / W_;
    const int t = w - b * W_;

    const int ti = lane >> 2;                 // 0..7
    const int tj = lane & 3;                  // 0..3
    const int base = TM * ti - TN * tj;
    int m = (t + 450 - base) % 900;
    if (m < 0) m += 900;

    float v = 0.f;
    int d = -1000;
    if (m <= 127)      d = m;
    else if (m >= 645) d = m - 900;
    if (d >= -255)
        v = g_part[((b * NTI + ti) * NTJ + tj) * 512 + d + 255];

#pragma unroll
    for (int off = 16; off; off >>= 1)
        v += __shfl_xor_sync(0xFFFFFFFFu, v, off);
    if (lane == 0) out[w] = v;
}

extern "C" void kernel_launch(void* const* d_in, const int* in_sizes, int n_in,
                              void* d_out, int out_size) {
    const float4* x1 = (const float4*)d_in[0];
    const float4* x2 = (const float4*)d_in[1];
    float* out = (float*)d_out;

    cudaFuncSetAttribute(corr_mma,
                         cudaFuncAttributeMaxDynamicSharedMemorySize, SMEM_BYTES);

    // Launch sequence [prepass, corr, dummy, reduce]: global launch index 5
    // (ncu -s 5 -c 1) lands on corr_mma in the second harness call.
    prepass_kernel<<<2048, 256>>>(x1, x2);
    corr_mma<<<B_ * NTI * NTJ, NTHREADS, SMEM_BYTES>>>(0);
    dummy_kernel<<<1, 32>>>();
    reduce_kernel<<<(B_ * W_ + 7) / 8, 256>>>(out);
}

// round 10
// speedup vs baseline: 1.8905x; 1.1291x over previous
#include <cuda_runtime.h>
#include <cstdint>

// out[b,t] = sum_w <x1[b,:,(t+w+450)%900,:], x2[b,:,w,:]>
//          = circular-diagonal sums of Gram G[b,i,j] = <a1_i, a2_j>.
// tf32 mma.sync. Prepass rounds inputs to tf32 once. GEMM: CTA 128x128,
// 256 threads, 3-stage cp.async pipeline (2-deep prefetch) in 96KB smem
// -> 2 CTAs/SM. Diagonal-bin epilogue; warp-shuffle reduce.

#define W_ 900
#define B_ 16
#define NTT 8         // tiles of 128 covering 1024
#define TM 128
#define KC 32         // K floats per stage
#define NK 32         // 1024 / KC
#define NTHREADS 256

#define STAGE_A 16384u          // 128 rows x 128B
#define STAGE   32768u          // A + B
#define SMEM_BYTES (3u * STAGE) // 98304

#define NELEM (B_ * 4 * W_ * 256)

__device__ float g_x1t[NELEM];
__device__ float g_x2t[NELEM];
__device__ float g_part[B_ * NTT * NTT * 256];

// ---------------- PTX helpers ----------------
__device__ __forceinline__ uint32_t smem_u32(const void* p) {
    uint32_t a;
    asm("{ .reg .u64 t; cvta.to.shared.u64 t, %1; cvt.u32.u64 %0, t; }" : "=r"(a) : "l"(p));
    return a;
}
__device__ __forceinline__ void cp16(uint32_t dst, const void* src, int sz) {
    asm volatile("cp.async.cg.shared.global [%0], [%1], 16, %2;"
                 :: "r"(dst), "l"(src), "r"(sz) : "memory");
}
__device__ __forceinline__ void cp_commit() {
    asm volatile("cp.async.commit_group;" ::: "memory");
}
__device__ __forceinline__ void cp_wait1() {
    asm volatile("cp.async.wait_group 1;" ::: "memory");
}
__device__ __forceinline__ void cp_wait0() {
    asm volatile("cp.async.wait_group 0;" ::: "memory");
}
__device__ __forceinline__ void ldm4(uint32_t* r, uint32_t a) {
    asm volatile("ldmatrix.sync.aligned.m8n8.x4.shared.b16 {%0,%1,%2,%3}, [%4];"
                 : "=r"(r[0]), "=r"(r[1]), "=r"(r[2]), "=r"(r[3]) : "r"(a));
}
__device__ __forceinline__ float tf32r(float x) {
    uint32_t o;
    asm("cvt.rna.tf32.f32 %0, %1;" : "=r"(o) : "f"(x));
    return __uint_as_float(o);
}
__device__ __forceinline__ void mma_t(float* c, const uint32_t* a, uint32_t b0, uint32_t b1) {
    asm volatile("mma.sync.aligned.m16n8k8.row.col.f32.tf32.tf32.f32 "
                 "{%0,%1,%2,%3}, {%4,%5,%6,%7}, {%8,%9}, {%0,%1,%2,%3};"
                 : "+f"(c[0]), "+f"(c[1]), "+f"(c[2]), "+f"(c[3])
                 : "r"(a[0]), "r"(a[1]), "r"(a[2]), "r"(a[3]), "r"(b0), "r"(b1));
}

// ---------------- prepass: fp32 -> tf32(rna) into scratch ----------------
__global__ __launch_bounds__(256)
void prepass_kernel(const float4* __restrict__ x1, const float4* __restrict__ x2) {
    const int n4 = NELEM / 4;
    float4* o1 = reinterpret_cast<float4*>(g_x1t);
    float4* o2 = reinterpret_cast<float4*>(g_x2t);
    for (int i = blockIdx.x * blockDim.x + threadIdx.x; i < n4;
         i += gridDim.x * blockDim.x) {
        float4 v = x1[i];
        o1[i] = make_float4(tf32r(v.x), tf32r(v.y), tf32r(v.z), tf32r(v.w));
        float4 u = x2[i];
        o2[i] = make_float4(tf32r(u.x), tf32r(u.y), tf32r(u.z), tf32r(u.w));
    }
}

// ---------------- stage loader: A 128 rows + B 128 rows, KC=32 ----------------
__device__ __forceinline__ void issue_stage(
    int s, int b, int i0, int j0, uint32_t sbase, int crow, int cchk)
{
    const int buf = s % 3;
    const int h  = (s * KC) >> 8;
    const int cb = (s * KC) & 255;
    const float* baseA = g_x1t + (size_t)(b * 4 + h) * W_ * 256 + cb + cchk * 4;
    const float* baseB = g_x2t + (size_t)(b * 4 + h) * W_ * 256 + cb + cchk * 4;
    const uint32_t dA0 = sbase + (uint32_t)buf * STAGE;
    const uint32_t dB0 = dA0 + STAGE_A;
#pragma unroll
    for (int q = 0; q < 4; ++q) {
        int row = q * 32 + crow;
        uint32_t doff = (uint32_t)row * 128u + (uint32_t)((cchk ^ (row & 7)) << 4);
        int ga = i0 + row;
        int gb = j0 + row;
        int szA = (ga < W_) ? 16 : 0; if (ga >= W_) ga = 0;
        int szB = (gb < W_) ? 16 : 0; if (gb >= W_) gb = 0;
        cp16(dA0 + doff, baseA + (size_t)ga * 256, szA);
        cp16(dB0 + doff, baseB + (size_t)gb * 256, szB);
    }
    cp_commit();
}

// ---------------- main GEMM kernel: 128x128 tile, 8 warps ----------------
__global__ __launch_bounds__(NTHREADS, 2)
void corr_mma(int unused) {
    extern __shared__ float smem[];
    const uint32_t sbase = smem_u32(smem);

    const int tid  = threadIdx.x;
    const int lane = tid & 31;
    const int wid  = tid >> 5;
    const int warp_m = wid & 1;    // 2 warps along i (64 rows each)
    const int warp_n = wid >> 1;   // 4 warps along j (32 cols each)

    const int bx = blockIdx.x;
    const int tj = bx & 7;
    const int ti = (bx >> 3) & 7;
    const int b  = bx >> 6;
    const int i0 = ti * TM;
    const int j0 = tj * TM;

    float acc[4][4][4];            // mt x nt x frag
#pragma unroll
    for (int m = 0; m < 4; ++m)
#pragma unroll
        for (int n = 0; n < 4; ++n)
#pragma unroll
            for (int k = 0; k < 4; ++k) acc[m][n][k] = 0.f;

    const int crow = tid >> 3;     // 0..31
    const int cchk = tid & 7;

    const int qm = lane >> 3;
    const int lr = lane & 7;
    const int qh = qm >> 1;        // k-chunk half
    const int ql = qm & 1;         // +8 rows
    const int rA = warp_m * 64 + ql * 8 + lr;   // + mt*16
    const int rB = warp_n * 32 + ql * 8 + lr;   // + np*16

    // 3-stage pipeline, 2-deep prefetch: issue 0,1 here; issue s+2 inside
    // the loop AFTER the barrier that proves buf (s+2)%3 is free.
    issue_stage(0, b, i0, j0, sbase, crow, cchk);
    issue_stage(1, b, i0, j0, sbase, crow, cchk);

    for (int s = 0; s < NK; ++s) {
        cp_wait1();        // stage s complete (s+1 may still be in flight)
        __syncthreads();   // + all warps done reading buf (s-1)%3 == (s+2)%3
        if (s + 2 < NK) issue_stage(s + 2, b, i0, j0, sbase, crow, cchk);
        else            cp_commit();   // keep wait_group arithmetic exact

        const uint32_t Ab = sbase + (uint32_t)(s % 3) * STAGE;
        const uint32_t Bb = Ab + STAGE_A;

#pragma unroll
        for (int kk = 0; kk < 4; ++kk) {
            uint32_t a[4][4], bf[2][4];
#pragma unroll
            for (int mt = 0; mt < 4; ++mt) {
                int row = rA + mt * 16;
                ldm4(a[mt], Ab + (uint32_t)row * 128u
                               + (uint32_t)(((2 * kk + qh) ^ (row & 7)) << 4));
            }
#pragma unroll
            for (int np = 0; np < 2; ++np) {
                int row = rB + np * 16;
                ldm4(bf[np], Bb + (uint32_t)row * 128u
                                + (uint32_t)(((2 * kk + qh) ^ (row & 7)) << 4));
            }
#pragma unroll
            for (int mt = 0; mt < 4; ++mt) {
#pragma unroll
                for (int nt = 0; nt < 4; ++nt) {
                    const int np = nt >> 1;
                    uint32_t b0 = (nt & 1) ? bf[np][1] : bf[np][0];
                    uint32_t b1 = (nt & 1) ? bf[np][3] : bf[np][2];
                    mma_t(acc[mt][nt], a[mt], b0, b1);
                }
            }
        }
    }

    // drain cp.async before smem reuse
    cp_wait0();
    __syncthreads();

    // ---------------- epilogue: stage 128x128 tile, bin diagonals ----------------
    float* stg = smem;                        // 128 x 132 floats = 67.6KB
#pragma unroll
    for (int mt = 0; mt < 4; ++mt) {
        const int row0 = warp_m * 64 + mt * 16 + (lane >> 2);
#pragma unroll
        for (int nt = 0; nt < 4; ++nt) {
            const int col = warp_n * 32 + nt * 8 + (lane & 3) * 2;
            stg[row0 * 132 + col]           = acc[mt][nt][0];
            stg[row0 * 132 + col + 1]       = acc[mt][nt][1];
            stg[(row0 + 8) * 132 + col]     = acc[mt][nt][2];
            stg[(row0 + 8) * 132 + col + 1] = acc[mt][nt][3];
        }
    }
    __syncthreads();

    if (tid < 255) {                          // d = i - j in [-127, 127]
        const int d = tid - 127;
        const int ilo = d > 0 ? d : 0;
        const int ihi = d < 0 ? 127 + d : 127;
        float sum = 0.f;
        for (int i = ilo; i <= ihi; ++i)
            sum += stg[i * 132 + (i - d)];
        g_part[bx * 256 + tid] = sum;
    }
}

// ---------------- reduce: one warp per (b,t), 64 tile pairs ----------------
__global__ __launch_bounds__(256)
void reduce_kernel(float* __restrict__ out) {
    const int w = blockIdx.x * 8 + (threadIdx.x >> 5);
    if (w >= B_ * W_) return;
    const int lane = threadIdx.x & 31;
    const int b = w / W_;
    const int t = w - b * W_;

    float v = 0.f;
#pragma unroll
    for (int half = 0; half < 2; ++half) {
        const int p  = half * 32 + lane;      // 0..63 = (ti, tj)
        const int ti = p >> 3;
        const int tj = p & 7;
        int m = (t + 450 - TM * (ti - tj)) % 900;
        if (m < 0) m += 900;
        int d = -1000;
        if (m <= 127)      d = m;
        else if (m >= 773) d = m - 900;
        if (d > -1000)
            v += g_part[((b * NTT + ti) * NTT + tj) * 256 + d + 127];
    }
#pragma unroll
    for (int off = 16; off; off >>= 1)
        v += __shfl_xor_sync(0xFFFFFFFFu, v, off);
    if (lane == 0) out[w] = v;
}

extern "C" void kernel_launch(void* const* d_in, const int* in_sizes, int n_in,
                              void* d_out, int out_size) {
    const float4* x1 = (const float4*)d_in[0];
    const float4* x2 = (const float4*)d_in[1];
    float* out = (float*)d_out;

    cudaFuncSetAttribute(corr_mma,
                         cudaFuncAttributeMaxDynamicSharedMemorySize, SMEM_BYTES);

    prepass_kernel<<<2048, 256>>>(x1, x2);
    corr_mma<<<B_ * NTT * NTT, NTHREADS, SMEM_BYTES>>>(0);
    reduce_kernel<<<(B_ * W_ + 7) / 8, 256>>>(out);
}

// round 11
// speedup vs baseline: 1.9435x; 1.0280x over previous
#include <cuda_runtime.h>
#include <cstdint>

// out[b,t] = sum_w <x1[b,:,(t+w+450)%900,:], x2[b,:,w,:]>
//          = circular-diagonal sums of Gram G[b,i,j] = <a1_i, a2_j>.
// tf32 mma.sync. Prepass rounds inputs to tf32 once. GEMM: CTA 128x128,
// 256 threads, 3-stage cp.async pipeline (2-deep prefetch), 96KB smem
// -> 2 CTAs/SM. Thin-tile guards skip MMA work in the 97%-padding tiles
// (ti==7 / tj==7: only 4 of 128 rows/cols valid since 900 = 7*128 + 4).

#define W_ 900
#define B_ 16
#define NTT 8         // tiles of 128 covering 1024
#define TM 128
#define KC 32         // K floats per stage
#define NK 32         // 1024 / KC
#define NTHREADS 256

#define STAGE_A 16384u          // 128 rows x 128B
#define STAGE   32768u          // A + B
#define SMEM_BYTES (3u * STAGE) // 98304

#define NELEM (B_ * 4 * W_ * 256)

__device__ float g_x1t[NELEM];
__device__ float g_x2t[NELEM];
__device__ float g_part[B_ * NTT * NTT * 256];

// ---------------- PTX helpers ----------------
__device__ __forceinline__ uint32_t smem_u32(const void* p) {
    uint32_t a;
    asm("{ .reg .u64 t; cvta.to.shared.u64 t, %1; cvt.u32.u64 %0, t; }" : "=r"(a) : "l"(p));
    return a;
}
__device__ __forceinline__ void cp16(uint32_t dst, const void* src, int sz) {
    asm volatile("cp.async.cg.shared.global [%0], [%1], 16, %2;"
                 :: "r"(dst), "l"(src), "r"(sz) : "memory");
}
__device__ __forceinline__ void cp_commit() {
    asm volatile("cp.async.commit_group;" ::: "memory");
}
__device__ __forceinline__ void cp_wait1() {
    asm volatile("cp.async.wait_group 1;" ::: "memory");
}
__device__ __forceinline__ void cp_wait0() {
    asm volatile("cp.async.wait_group 0;" ::: "memory");
}
__device__ __forceinline__ void ldm4(uint32_t* r, uint32_t a) {
    asm volatile("ldmatrix.sync.aligned.m8n8.x4.shared.b16 {%0,%1,%2,%3}, [%4];"
                 : "=r"(r[0]), "=r"(r[1]), "=r"(r[2]), "=r"(r[3]) : "r"(a));
}
__device__ __forceinline__ float tf32r(float x) {
    uint32_t o;
    asm("cvt.rna.tf32.f32 %0, %1;" : "=r"(o) : "f"(x));
    return __uint_as_float(o);
}
__device__ __forceinline__ void mma_t(float* c, const uint32_t* a, uint32_t b0, uint32_t b1) {
    asm volatile("mma.sync.aligned.m16n8k8.row.col.f32.tf32.tf32.f32 "
                 "{%0,%1,%2,%3}, {%4,%5,%6,%7}, {%8,%9}, {%0,%1,%2,%3};"
                 : "+f"(c[0]), "+f"(c[1]), "+f"(c[2]), "+f"(c[3])
                 : "r"(a[0]), "r"(a[1]), "r"(a[2]), "r"(a[3]), "r"(b0), "r"(b1));
}

// ---------------- prepass: fp32 -> tf32(rna) into scratch ----------------
__global__ __launch_bounds__(256)
void prepass_kernel(const float4* __restrict__ x1, const float4* __restrict__ x2) {
    const int n4 = NELEM / 4;
    float4* o1 = reinterpret_cast<float4*>(g_x1t);
    float4* o2 = reinterpret_cast<float4*>(g_x2t);
    for (int i = blockIdx.x * blockDim.x + threadIdx.x; i < n4;
         i += gridDim.x * blockDim.x) {
        float4 v = x1[i];
        o1[i] = make_float4(tf32r(v.x), tf32r(v.y), tf32r(v.z), tf32r(v.w));
        float4 u = x2[i];
        o2[i] = make_float4(tf32r(u.x), tf32r(u.y), tf32r(u.z), tf32r(u.w));
    }
}

// ---------------- stage loader: A 128 rows + B 128 rows, KC=32 ----------------
__device__ __forceinline__ void issue_stage(
    int s, int b, int i0, int j0, uint32_t sbase, int crow, int cchk)
{
    const int buf = s % 3;
    const int h  = (s * KC) >> 8;
    const int cb = (s * KC) & 255;
    const float* baseA = g_x1t + (size_t)(b * 4 + h) * W_ * 256 + cb + cchk * 4;
    const float* baseB = g_x2t + (size_t)(b * 4 + h) * W_ * 256 + cb + cchk * 4;
    const uint32_t dA0 = sbase + (uint32_t)buf * STAGE;
    const uint32_t dB0 = dA0 + STAGE_A;
#pragma unroll
    for (int q = 0; q < 4; ++q) {
        int row = q * 32 + crow;
        uint32_t doff = (uint32_t)row * 128u + (uint32_t)((cchk ^ (row & 7)) << 4);
        int ga = i0 + row;
        int gb = j0 + row;
        int szA = (ga < W_) ? 16 : 0; if (ga >= W_) ga = 0;
        int szB = (gb < W_) ? 16 : 0; if (gb >= W_) gb = 0;
        cp16(dA0 + doff, baseA + (size_t)ga * 256, szA);
        cp16(dB0 + doff, baseB + (size_t)gb * 256, szB);
    }
    cp_commit();
}

// ---------------- main GEMM kernel: 128x128 tile, 8 warps ----------------
__global__ __launch_bounds__(NTHREADS, 2)
void corr_mma(int unused) {
    extern __shared__ float smem[];
    const uint32_t sbase = smem_u32(smem);

    const int tid  = threadIdx.x;
    const int lane = tid & 31;
    const int wid  = tid >> 5;
    const int warp_m = wid & 1;    // 2 warps along i (64 rows each)
    const int warp_n = wid >> 1;   // 4 warps along j (32 cols each)

    const int bx = blockIdx.x;
    const int tj = bx & 7;
    const int ti = (bx >> 3) & 7;
    const int b  = bx >> 6;
    const int i0 = ti * TM;
    const int j0 = tj * TM;

    // Thin-tile guards: tile row/col 7 has only 4 valid lines (896..899).
    // Valid rows live in warp_m==0, mt==0 (tile rows 0..15); valid cols in
    // warp_n==0, nt==0 (tile cols 0..7). Loads zfill the rest already.
    const bool full_tile = (ti != 7) && (tj != 7);
    const int MT = (ti != 7) ? 4 : ((warp_m == 0) ? 1 : 0);
    const int NT = (tj != 7) ? 4 : ((warp_n == 0) ? 1 : 0);
    const int NP = (NT + 1) >> 1;
    const bool active = (MT > 0) && (NT > 0);

    float acc[4][4][4];            // mt x nt x frag
#pragma unroll
    for (int m = 0; m < 4; ++m)
#pragma unroll
        for (int n = 0; n < 4; ++n)
#pragma unroll
            for (int k = 0; k < 4; ++k) acc[m][n][k] = 0.f;

    const int crow = tid >> 3;     // 0..31
    const int cchk = tid & 7;

    const int qm = lane >> 3;
    const int lr = lane & 7;
    const int qh = qm >> 1;        // k-chunk half
    const int ql = qm & 1;         // +8 rows
    const int rA = warp_m * 64 + ql * 8 + lr;   // + mt*16
    const int rB = warp_n * 32 + ql * 8 + lr;   // + np*16

    // 3-stage pipeline, 2-deep prefetch.
    issue_stage(0, b, i0, j0, sbase, crow, cchk);
    issue_stage(1, b, i0, j0, sbase, crow, cchk);

    for (int s = 0; s < NK; ++s) {
        cp_wait1();        // stage s complete (s+1 may still be in flight)
        __syncthreads();   // all warps done reading buf (s-1)%3 == (s+2)%3
        if (s + 2 < NK) issue_stage(s + 2, b, i0, j0, sbase, crow, cchk);
        else            cp_commit();   // keep wait_group arithmetic exact

        const uint32_t Ab = sbase + (uint32_t)(s % 3) * STAGE;
        const uint32_t Bb = Ab + STAGE_A;

        if (full_tile) {
            // -------- hot path: fully unrolled 4x4 --------
#pragma unroll
            for (int kk = 0; kk < 4; ++kk) {
                uint32_t a[4][4], bf[2][4];
#pragma unroll
                for (int mt = 0; mt < 4; ++mt) {
                    int row = rA + mt * 16;
                    ldm4(a[mt], Ab + (uint32_t)row * 128u
                                   + (uint32_t)(((2 * kk + qh) ^ (row & 7)) << 4));
                }
#pragma unroll
                for (int np = 0; np < 2; ++np) {
                    int row = rB + np * 16;
                    ldm4(bf[np], Bb + (uint32_t)row * 128u
                                    + (uint32_t)(((2 * kk + qh) ^ (row & 7)) << 4));
                }
#pragma unroll
                for (int mt = 0; mt < 4; ++mt) {
#pragma unroll
                    for (int nt = 0; nt < 4; ++nt) {
                        const int np = nt >> 1;
                        uint32_t b0 = (nt & 1) ? bf[np][1] : bf[np][0];
                        uint32_t b1 = (nt & 1) ? bf[np][3] : bf[np][2];
                        mma_t(acc[mt][nt], a[mt], b0, b1);
                    }
                }
            }
        } else if (active) {
            // -------- thin path: runtime-bounded (rare blocks) --------
            for (int kk = 0; kk < 4; ++kk) {
                uint32_t a[4][4], bf[2][4];
                for (int mt = 0; mt < MT; ++mt) {
                    int row = rA + mt * 16;
                    ldm4(a[mt], Ab + (uint32_t)row * 128u
                                   + (uint32_t)(((2 * kk + qh) ^ (row & 7)) << 4));
                }
                for (int np = 0; np < NP; ++np) {
                    int row = rB + np * 16;
                    ldm4(bf[np], Bb + (uint32_t)row * 128u
                                    + (uint32_t)(((2 * kk + qh) ^ (row & 7)) << 4));
                }
                for (int mt = 0; mt < MT; ++mt) {
                    for (int nt = 0; nt < NT; ++nt) {
                        const int np = nt >> 1;
                        uint32_t b0 = (nt & 1) ? bf[np][1] : bf[np][0];
                        uint32_t b1 = (nt & 1) ? bf[np][3] : bf[np][2];
                        mma_t(acc[mt][nt], a[mt], b0, b1);
                    }
                }
            }
        }
        // warps with MT==0 || NT==0 skip compute entirely (still sync/load)
    }

    // drain cp.async before smem reuse
    cp_wait0();
    __syncthreads();

    // ---------------- epilogue: stage 128x128 tile, bin diagonals ----------------
    float* stg = smem;                        // 128 x 132 floats = 67.6KB
#pragma unroll
    for (int mt = 0; mt < 4; ++mt) {
        const int row0 = warp_m * 64 + mt * 16 + (lane >> 2);
#pragma unroll
        for (int nt = 0; nt < 4; ++nt) {
            const int col = warp_n * 32 + nt * 8 + (lane & 3) * 2;
            stg[row0 * 132 + col]           = acc[mt][nt][0];
            stg[row0 * 132 + col + 1]       = acc[mt][nt][1];
            stg[(row0 + 8) * 132 + col]     = acc[mt][nt][2];
            stg[(row0 + 8) * 132 + col + 1] = acc[mt][nt][3];
        }
    }
    __syncthreads();

    if (tid < 255) {                          // d = i - j in [-127, 127]
        const int d = tid - 127;
        const int ilo = d > 0 ? d : 0;
        const int ihi = d < 0 ? 127 + d : 127;
        float sum = 0.f;
        for (int i = ilo; i <= ihi; ++i)
            sum += stg[i * 132 + (i - d)];
        g_part[bx * 256 + tid] = sum;
    }
}

// ---------------- reduce: one warp per (b,t), 64 tile pairs ----------------
__global__ __launch_bounds__(256)
void reduce_kernel(float* __restrict__ out) {
    const int w = blockIdx.x * 8 + (threadIdx.x >> 5);
    if (w >= B_ * W_) return;
    const int lane = threadIdx.x & 31;
    const int b = w / W_;
    const int t = w - b * W_;

    float v = 0.f;
#pragma unroll
    for (int half = 0; half < 2; ++half) {
        const int p  = half * 32 + lane;      // 0..63 = (ti, tj)
        const int ti = p >> 3;
        const int tj = p & 7;
        int m = (t + 450 - TM * (ti - tj)) % 900;
        if (m < 0) m += 900;
        int d = -1000;
        if (m <= 127)      d = m;
        else if (m >= 773) d = m - 900;
        if (d > -1000)
            v += g_part[((b * NTT + ti) * NTT + tj) * 256 + d + 127];
    }
#pragma unroll
    for (int off = 16; off; off >>= 1)
        v += __shfl_xor_sync(0xFFFFFFFFu, v, off);
    if (lane == 0) out[w] = v;
}

extern "C" void kernel_launch(void* const* d_in, const int* in_sizes, int n_in,
                              void* d_out, int out_size) {
    const float4* x1 = (const float4*)d_in[0];
    const float4* x2 = (const float4*)d_in[1];
    float* out = (float*)d_out;

    cudaFuncSetAttribute(corr_mma,
                         cudaFuncAttributeMaxDynamicSharedMemorySize, SMEM_BYTES);

    prepass_kernel<<<2048, 256>>>(x1, x2);
    corr_mma<<<B_ * NTT * NTT, NTHREADS, SMEM_BYTES>>>(0);
    reduce_kernel<<<(B_ * W_ + 7) / 8, 256>>>(out);
}

// round 13
// speedup vs baseline: 2.3936x; 1.2316x over previous
#include <cuda_runtime.h>
#include <cstdint>

// out[b,t] = sum_w <x1[b,:,(t+w+450)%900,:], x2[b,:,w,:]>
// Spectral method: per channel (b,h,c), circular cross-correlation via FFT-900.
//   z = x1 + i*x2 (one complex FFT per channel pair, 16384 total)
//   X1 = (Z(k)+conj(Z(-k)))/2,  X2 = (Z(k)-conj(Z(-k)))/(2i)
//   S[k] = sum_ch (-1)^k * X1(k)*conj(X2(k))   (Hermitian: keep k<=450)
//   out[t] = (1/900) * Re( sum_k S[k] e^{+2*pi*i*k*t/900} )
// FFT-900 = 30x30 Cooley-Tukey; DFT-30 = 5x6 CT with hardcoded W5/W6.

#define W_ 900
#define B_ 16
#define NCH 16384            // 16 * 1024 channels
#define NELEM (NCH * W_)

__device__ float  g_x1t[NELEM];        // transposed: [channel][w]
__device__ float  g_x2t[NELEM];
__device__ float2 g_W900[W_];          // e^{-2*pi*i*j/900}
__device__ float  g_spart[2048 * 452 * 2];  // per-(b,grp) partial spectra

// ---------------- small-DFT constants (e^{-2 pi i j / N}) ----------------
__device__ constexpr float W6re[6] = { 1.f,  0.5f, -0.5f, -1.f, -0.5f,  0.5f };
__device__ constexpr float W6im[6] = { 0.f, -0.86602540378f, -0.86602540378f, 0.f,
                                       0.86602540378f,  0.86602540378f };
__device__ constexpr float W5re[5] = { 1.f,  0.30901699437f, -0.80901699437f,
                                      -0.80901699437f,  0.30901699437f };
__device__ constexpr float W5im[5] = { 0.f, -0.95105651630f, -0.58778525229f,
                                       0.58778525229f,  0.95105651630f };

__device__ __forceinline__ float2 cmul(float2 a, float2 b) {
    return make_float2(a.x * b.x - a.y * b.y, a.x * b.y + a.y * b.x);
}

// DFT-30 over v[0..29] (natural order in and out), via 30 = 5 x 6.
// m = m1 + 5*m2 (m1<5, m2<6), q = q2 + 6*q1 (q2<6, q1<5).
// MODE 0: stage-1 row r=lane: store with level-1 twiddle W900^{lane*q} at
//         zw[lane*32 + ((q+lane)&31)].
// MODE 1: stage-2 col c=lane: store plain at zw[q*32 + ((lane+q)&31)].
template <int MODE>
__device__ __forceinline__ void dft30_io(float2* v, float2* zw,
                                         const float2* Wsh, int lane) {
    // stage a: DFT-6 over m2 within each m1-group, in place, + W30 twiddle
#pragma unroll
    for (int m1 = 0; m1 < 5; ++m1) {
        float2 e[6];
#pragma unroll
        for (int m2 = 0; m2 < 6; ++m2) e[m2] = v[m1 + 5 * m2];
#pragma unroll
        for (int q2 = 0; q2 < 6; ++q2) {
            float re = 0.f, im = 0.f;
#pragma unroll
            for (int m2 = 0; m2 < 6; ++m2) {
                const float wr = W6re[(m2 * q2) % 6];
                const float wi = W6im[(m2 * q2) % 6];
                re += e[m2].x * wr - e[m2].y * wi;
                im += e[m2].x * wi + e[m2].y * wr;
            }
            float2 t = make_float2(re, im);
            if (m1 * q2 != 0) t = cmul(t, Wsh[30 * m1 * q2]);  // W30^{m1 q2}
            v[m1 + 5 * q2] = t;
        }
    }
    // stage b: DFT-5 over m1 for each q2; emit q = q2 + 6*q1
#pragma unroll
    for (int q2 = 0; q2 < 6; ++q2) {
        float2 f[5];
#pragma unroll
        for (int m1 = 0; m1 < 5; ++m1) f[m1] = v[m1 + 5 * q2];
#pragma unroll
        for (int q1 = 0; q1 < 5; ++q1) {
            float re = 0.f, im = 0.f;
#pragma unroll
            for (int m1 = 0; m1 < 5; ++m1) {
                const float wr = W5re[(m1 * q1) % 5];
                const float wi = W5im[(m1 * q1) % 5];
                re += f[m1].x * wr - f[m1].y * wi;
                im += f[m1].x * wi + f[m1].y * wr;
            }
            const int q = q2 + 6 * q1;
            float2 o = make_float2(re, im);
            if (MODE == 0) {
                o = cmul(o, Wsh[lane * q]);             // W900^{r q}
                zw[lane * 32 + ((q + lane) & 31)] = o;
            } else {
                zw[q * 32 + ((lane + q) & 31)] = o;
            }
        }
    }
}

// ---------------- kernel 1: transpose to channel-major + twiddle fill ----
__global__ __launch_bounds__(256)
void transpose_kernel(const float* __restrict__ x1, const float* __restrict__ x2) {
    __shared__ float tile[32][33];
    const int tx = threadIdx.x, ty = threadIdx.y;
    const int tensor = blockIdx.z >> 6;
    const int bh = blockIdx.z & 63;
    const float* src = (tensor ? x2 : x1) + (size_t)bh * W_ * 256;
    float* dst = (tensor ? g_x2t : g_x1t) + (size_t)bh * 256 * W_;
    const int w0 = blockIdx.x * 32, c0 = blockIdx.y * 32;

#pragma unroll
    for (int i = 0; i < 4; ++i) {
        int w = w0 + ty + i * 8;
        if (w < W_) tile[ty + i * 8][tx] = src[(size_t)w * 256 + c0 + tx];
    }
    __syncthreads();
#pragma unroll
    for (int i = 0; i < 4; ++i) {
        int wt = w0 + tx;
        int ct = c0 + ty + i * 8;
        if (wt < W_) dst[(size_t)ct * W_ + wt] = tile[tx][ty + i * 8];
    }

    if (blockIdx.x == 0 && blockIdx.y == 0 && blockIdx.z == 0) {
        int tid = ty * 32 + tx;
        for (int j = tid; j < W_; j += 256) {
            double s, c;
            sincospi(-2.0 * (double)j / 900.0, &s, &c);
            g_W900[j] = make_float2((float)c, (float)s);
        }
    }
}

// ---------------- kernel 2: per-channel FFT + combine + partial spectra --
// grid 2048 = b*128 + grp; 8 warps; warp = channel b*1024 + grp*8 + wid.
__global__ __launch_bounds__(256)
void fft_kernel(int unused) {
    extern __shared__ float2 sm[];
    // layout (float2 units): zw 8*960 | W900 904 | Pbuf 8*452
    float2* Wsh  = sm + 7680;
    float2* Pall = sm + 7680 + 904;

    const int tid  = threadIdx.x;
    const int lane = tid & 31;
    const int wid  = tid >> 5;
    const int b    = blockIdx.x >> 7;
    const int grp  = blockIdx.x & 127;
    const int ch   = b * 1024 + grp * 8 + wid;

    float2* zw = sm + wid * 960;
    float2* Pb = Pall + wid * 452;

    for (int j = tid; j < W_; j += 256) Wsh[j] = g_W900[j];
    __syncthreads();

    // load packed signal: z[n] = x1 + i x2; n = r + 30*c -> zw[r][swz(c,r)]
    const float* p1 = g_x1t + (size_t)ch * W_;
    const float* p2 = g_x2t + (size_t)ch * W_;
    for (int idx = lane; idx < W_; idx += 32) {
        int r = idx % 30, c = idx / 30;
        zw[r * 32 + ((c + r) & 31)] = make_float2(p1[idx], p2[idx]);
    }
    __syncwarp();

    // stage 1: DFT-30 along rows (over n2), + twiddle W900^{r*k2}
    if (lane < 30) {
        float2 v[30];
#pragma unroll
        for (int c = 0; c < 30; ++c) v[c] = zw[lane * 32 + ((c + lane) & 31)];
        dft30_io<0>(v, zw, Wsh, lane);
    }
    __syncwarp();

    // stage 2: DFT-30 along columns (over n1); Z[k2 + 30*k1] -> zw[k1][k2]
    if (lane < 30) {
        float2 v[30];
#pragma unroll
        for (int m = 0; m < 30; ++m) v[m] = zw[m * 32 + ((lane + m) & 31)];
        dft30_io<1>(v, zw, Wsh, lane);
    }
    __syncwarp();

    // combine: P[k] = (-1)^k X1(k) conj(X2(k)), k = 0..450
    for (int k = lane; k <= 450; k += 32) {
        int m = (W_ - k) % W_;
        float2 A  = zw[(k / 30) * 32 + ((k % 30 + k / 30) & 31)];
        float2 Zm = zw[(m / 30) * 32 + ((m % 30 + m / 30) & 31)];
        float2 X1 = make_float2(0.5f * (A.x + Zm.x), 0.5f * (A.y - Zm.y));
        float2 D  = make_float2(0.5f * (A.x - Zm.x), 0.5f * (A.y + Zm.y));
        // X2 = -i*D; P = X1*conj(X2) with conj(X2) = (D.y, D.x)
        float pr = X1.x * D.y - X1.y * D.x;
        float pi = X1.x * D.x + X1.y * D.y;
        float sg = (k & 1) ? -1.f : 1.f;
        Pb[k] = make_float2(sg * pr, sg * pi);
    }
    __syncthreads();

    // CTA-reduce 8 warps -> partial spectrum for this (b, grp)
    float2* part = reinterpret_cast<float2*>(g_spart) + (size_t)blockIdx.x * 452;
    for (int k = tid; k <= 450; k += 256) {
        float2 s = make_float2(0.f, 0.f);
#pragma unroll
        for (int w = 0; w < 8; ++w) {
            float2 p = Pall[w * 452 + k];
            s.x += p.x; s.y += p.y;
        }
        part[k] = s;
    }
}

__global__ void dummy_kernel(int unused) {}

// ---------------- kernel 3: reduce partials + inverse DFT to out ---------
// grid (16, 4): b, quarter of t-range (225 outputs each)
__global__ __launch_bounds__(256)
void final_kernel(float* __restrict__ out) {
    __shared__ float2 S[452];
    __shared__ float2 Wsh[W_];
    const int tid = threadIdx.x;
    const int b = blockIdx.x;
    const int q = blockIdx.y;

    for (int j = tid; j < W_; j += 256) Wsh[j] = g_W900[j];
    const float2* part = reinterpret_cast<const float2*>(g_spart);
    for (int k = tid; k <= 450; k += 256) {
        float2 s = make_float2(0.f, 0.f);
        for (int g = 0; g < 128; ++g) {
            float2 p = part[(size_t)(b * 128 + g) * 452 + k];
            s.x += p.x; s.y += p.y;
        }
        S[k] = s;
    }
    __syncthreads();

    if (tid < 225) {
        const int t = q * 225 + tid;
        float acc = 0.f;
        int idx = 0;                       // (k*t) % 900, incremental
        for (int k = 0; k <= 450; ++k) {
            float2 W = Wsh[idx];
            float2 s = S[k];
            // Re(S * e^{+i theta}) with W900 = e^{-i theta}: s.x*W.x + s.y*W.y
            float term = s.x * W.x + s.y * W.y;
            acc += (k == 0 || k == 450) ? term : 2.f * term;
            idx += t; if (idx >= W_) idx -= W_;
        }
        out[b * W_ + t] = acc * (1.f / 900.f);
    }
}

extern "C" void kernel_launch(void* const* d_in, const int* in_sizes, int n_in,
                              void* d_out, int out_size) {
    const float* x1 = (const float*)d_in[0];
    const float* x2 = (const float*)d_in[1];
    float* out = (float*)d_out;

    cudaFuncSetAttribute(fft_kernel,
                         cudaFuncAttributeMaxDynamicSharedMemorySize, 97664);

    transpose_kernel<<<dim3(29, 8, 128), dim3(32, 8)>>>(x1, x2);
    fft_kernel<<<2048, 256, 97664>>>(0);
    dummy_kernel<<<1, 32>>>(0);            // aligns ncu -s 5 onto fft_kernel
    final_kernel<<<dim3(16, 4), 256>>>(out);
}